// round 7
// baseline (speedup 1.0000x reference)
#include <cuda_runtime.h>
#include <cuda_bf16.h>

#define MAX_ATOMS 200000

// packed per-atom data: {charge*sqrt(ELE_FACTOR), sqrt(c6), 0.5*r0, unused}
__device__ float4 g_atom[MAX_ATOMS];

// vectorized pack: 4 atoms per thread
__global__ __launch_bounds__(256) void pack_atoms_kernel(
    const float4* __restrict__ charge4,
    const float4* __restrict__ c64,
    const float4* __restrict__ r04,
    int n4, int n)
{
    int i = blockIdx.x * blockDim.x + threadIdx.x;
    if (i < n4) {
        float4 q = charge4[i];
        float4 c = c64[i];
        float4 r = r04[i];
        g_atom[4 * i + 0] = make_float4(q.x * 18.2226124f, sqrtf(c.x), 0.5f * r.x, 0.0f);
        g_atom[4 * i + 1] = make_float4(q.y * 18.2226124f, sqrtf(c.y), 0.5f * r.y, 0.0f);
        g_atom[4 * i + 2] = make_float4(q.z * 18.2226124f, sqrtf(c.z), 0.5f * r.z, 0.0f);
        g_atom[4 * i + 3] = make_float4(q.w * 18.2226124f, sqrtf(c.w), 0.5f * r.w, 0.0f);
    }
    int t = 4 * n4 + i;
    if (i < (n - 4 * n4)) {
        const float* charge = (const float*)charge4;
        const float* c6 = (const float*)c64;
        const float* r0 = (const float*)r04;
        g_atom[t] = make_float4(charge[t] * 18.2226124f, sqrtf(c6[t]), 0.5f * r0[t], 0.0f);
    }
}

__global__ __launch_bounds__(256) void bamboo_edge_kernel(
    const int* __restrict__ row,
    const int* __restrict__ col,
    const float* __restrict__ dij,
    float* __restrict__ out,
    int E)
{
    __shared__ float buf[8][96];   // one 384B transpose buffer per warp

    int lane = threadIdx.x & 31;
    int warp = threadIdx.x >> 5;
    int base = blockIdx.x * blockDim.x + (warp << 5);   // first edge of this warp
    int i = base + lane;
    bool fullwarp = (base + 32 <= E);
    bool active = (i < E);

    // ---- constants ----
    const float EWALD_F = 1.12837917f;
    const float EWALD_P = 0.3275911f;
    const float A0 = 0.254829592f, A1 = -0.284496736f, A2 = 1.421413741f,
                A3 = -1.453152027f, A4 = 1.061405429f;
    const float COUL_BETA = 18.7f;
    const float COUL_R0 = 2.2f;
    const float G_EWALD = 0.3f;
    const float DISP_C = 1.0f / 1000000.0f;
    const float R45_6 = 8303.765625f;   // 4.5^6

    // ---- pre-sync: streaming loads (independent of pack kernel) ----
    int ri = 0, ci = 0;
    float dx = 0.f, dy = 0.f, dz = 0.f;
    if (active) {
        ri = __ldcs(&row[i]);
        ci = __ldcs(&col[i]);
    }
    if (fullwarp) {
        // coalesced: 3 wavefronts instead of 9
        #pragma unroll
        for (int k = 0; k < 3; k++)
            buf[warp][k * 32 + lane] = __ldcs(&dij[(size_t)3 * base + k * 32 + lane]);
        __syncwarp();
        dx = buf[warp][3 * lane + 0];
        dy = buf[warp][3 * lane + 1];
        dz = buf[warp][3 * lane + 2];
    } else if (active) {
        dx = __ldcs(&dij[3 * i + 0]);
        dy = __ldcs(&dij[3 * i + 1]);
        dz = __ldcs(&dij[3 * i + 2]);
    }

    // wait for pack_atoms_kernel completion (PDL)
    cudaGridDependencySynchronize();

    if (!active) return;

    float4 ai = g_atom[ri];
    float4 aj = g_atom[ci];

    float r2 = dx * dx + dy * dy + dz * dz;
    float rinv = rsqrtf(r2);
    float rij = r2 * rinv;
    float rinv2 = rinv * rinv;

    // ---- Coulomb ----
    float prefactor = ai.x * aj.x * rinv;

    float x = (COUL_BETA / COUL_R0) * (rij - COUL_R0);
    float ex = __expf(x);
    float damp = ex / (1.0f + ex);
    float sp = __logf(1.0f + ex) * (1.0f / COUL_BETA);
    float s = rij * (1.0f / COUL_R0) / (1.0f + sp);

    float ecoul = prefactor * s;
    float fcoul = prefactor * damp * s * s;

    float grij = G_EWALD * rij;
    float expm2 = __expf(-grij * grij);
    float t = 1.0f / (1.0f + EWALD_P * grij);
    float erfc = t * (A0 + t * (A1 + t * (A2 + t * (A3 + t * A4)))) * expm2;
    ecoul += prefactor * (erfc - 1.0f);
    fcoul += prefactor * (erfc + EWALD_F * grij * expm2 - 1.0f);

    float cf = fcoul * rinv2;

    // ---- Dispersion ----
    float c6ij = ai.y * aj.y;
    float r0ij = ai.z + aj.z;

    float r4 = r2 * r2;
    float r5 = r4 * rij;
    float r6 = r4 * r2 + R45_6;
    float r6inv = 1.0f / r6;

    float e = __expf(rij - 2.5f * r0ij);
    float einv = 1.0f / (1.0f + e);
    float cso = 0.85f + 0.82f * einv;

    float edisp = -c6ij * r6inv * cso + c6ij * DISP_C;
    float fdisp = -6.0f * c6ij * r5 * r6inv * r6inv * cso
                  - c6ij * r6inv * (0.82f * e * einv * einv);
    float df = fdisp * rinv;

    // ---- outputs: [ecoul E][coul_fij 3E][edisp E][disp_fij 3E] ----
    float* ecoul_o = out;
    float* cfij_o  = out + (size_t)E;
    float* edisp_o = out + (size_t)4 * E;
    float* dfij_o  = out + (size_t)5 * E;

    __stcs(&ecoul_o[i], ecoul);
    __stcs(&edisp_o[i], edisp);

    if (fullwarp) {
        // cfij: transpose through smem, 3 coalesced wavefronts instead of 9
        __syncwarp();
        buf[warp][3 * lane + 0] = dx * cf;
        buf[warp][3 * lane + 1] = dy * cf;
        buf[warp][3 * lane + 2] = dz * cf;
        __syncwarp();
        #pragma unroll
        for (int k = 0; k < 3; k++)
            __stcs(&cfij_o[(size_t)3 * base + k * 32 + lane], buf[warp][k * 32 + lane]);

        // dfij: same
        __syncwarp();
        buf[warp][3 * lane + 0] = dx * df;
        buf[warp][3 * lane + 1] = dy * df;
        buf[warp][3 * lane + 2] = dz * df;
        __syncwarp();
        #pragma unroll
        for (int k = 0; k < 3; k++)
            __stcs(&dfij_o[(size_t)3 * base + k * 32 + lane], buf[warp][k * 32 + lane]);
    } else {
        __stcs(&cfij_o[3 * i + 0], dx * cf);
        __stcs(&cfij_o[3 * i + 1], dy * cf);
        __stcs(&cfij_o[3 * i + 2], dz * cf);
        __stcs(&dfij_o[3 * i + 0], dx * df);
        __stcs(&dfij_o[3 * i + 1], dy * df);
        __stcs(&dfij_o[3 * i + 2], dz * df);
    }
}

extern "C" void kernel_launch(void* const* d_in, const int* in_sizes, int n_in,
                              void* d_out, int out_size)
{
    const int*   row    = (const int*)d_in[0];
    const int*   col    = (const int*)d_in[1];
    const float* dij    = (const float*)d_in[2];
    const float* charge = (const float*)d_in[3];
    const float* c6     = (const float*)d_in[4];
    const float* r0     = (const float*)d_in[5];
    float* out = (float*)d_out;

    int E = in_sizes[0];
    int n_atoms = in_sizes[3];
    int n4 = n_atoms / 4;

    int threads = 256;
    int pack_blocks = (n4 + threads - 1) / threads;
    if (pack_blocks < 1) pack_blocks = 1;
    pack_atoms_kernel<<<pack_blocks, threads>>>(
        (const float4*)charge, (const float4*)c6, (const float4*)r0, n4, n_atoms);

    cudaLaunchConfig_t cfg = {};
    cfg.gridDim = dim3((E + threads - 1) / threads, 1, 1);
    cfg.blockDim = dim3(threads, 1, 1);
    cfg.dynamicSmemBytes = 0;
    cfg.stream = 0;
    cudaLaunchAttribute attr[1];
    attr[0].id = cudaLaunchAttributeProgrammaticStreamSerialization;
    attr[0].val.programmaticStreamSerializationAllowed = 1;
    cfg.attrs = attr;
    cfg.numAttrs = 1;
    cudaLaunchKernelEx(&cfg, bamboo_edge_kernel, row, col, dij, out, E);
}